// round 12
// baseline (speedup 1.0000x reference)
#include <cuda_runtime.h>
#include <math.h>

#define NN 50000
#define NE 800000
#define EPSV 1e-5

// ---------------- scratch (__device__ globals; no runtime alloc) ----------------
__device__ double g_degd[NN];          // fp64 degree (deterministic to 1e-16)
__device__ float  g_degf[NN];          // fp32 snapshot for mincut_den
__device__ float  g_E[NN * 64];
__device__ float  g_hlin[NN * 64];
__device__ float  g_hcat[NN * 192];
__device__ float  g_ssmf[NN * 16];     // fp32 ssm (feeds key kernel — FROZEN)
__device__ float  g_emb[256 * 3088];
__device__ float  g_h1pre[256 * 128];
__device__ float  g_sub2f[16 * 256];   // fp32 sort keys (winning realization — FROZEN)

// CSR structures (built once per launch; rows canonically sorted -> deterministic)
__device__ int    g_cnt[NN];
__device__ int    g_cur[NN];
__device__ int    g_rowoff[NN + 1];
__device__ int2   g_csre[NE];          // (col, weight-bits)
__device__ int    g_rowtmp[50176];
__device__ int    g_bsum[64];

// fp64 accumulator zone (zeroed by k_init)
#define D_EMB    0      // 128
#define D_G0     128    // 128
#define D_G1     256    // 128
#define D_GL     384    // 384
#define D_COLSUM 768    // 16
#define D_SS     784    // 256
#define D_NUM    1040   // 1
#define D_DEN    1041   // 1
#define D_OUT    1048   // 3072
#define D_TOTAL  4120
__device__ double g_d[D_TOTAL];

// GraphNorm affine from fp64 stats (identical math across rounds)
__device__ __forceinline__ void affine_pair(const double* sums, const float* w,
        const float* b, const float* ms, int C, double invN, int c,
        float* a_out, float* c_out) {
    double mu = sums[c] * invN;
    double ex2 = sums[C + c] * invN;
    double m = (double)ms[c];
    double var = ex2 - 2.0 * m * mu * mu + m * m * mu * mu;
    double a = (double)w[c] / sqrt(var + EPSV);
    *a_out = (float)a;
    *c_out = (float)((double)b[c] - a * m * mu);
}

// ---------------- kernels ----------------

// one init kernel replaces 5 memsets
__global__ void k_init() {
    int i = blockIdx.x * blockDim.x + threadIdx.x;
    int stride = gridDim.x * blockDim.x;
    for (int j = i; j < NN; j += stride) {
        g_degd[j] = 0.0; g_cnt[j] = 0; g_cur[j] = 0;
    }
    for (int j = i; j < 256 * 128; j += stride) g_h1pre[j] = 0.f;
    for (int j = i; j < D_TOTAL; j += stride) g_d[j] = 0.0;
}

__global__ void k_deg(const int* ei, const float* ew) {
    int e = blockIdx.x * blockDim.x + threadIdx.x;
    if (e < NE) {
        atomicAdd(&g_degd[ei[e]], (double)ew[e]);
        atomicAdd(&g_cnt[ei[e]], 1);
    }
}

// scan phase 1: per-1024-chunk inclusive scan + block totals
__global__ void k_scan1() {
    __shared__ int sh[1024];
    int t = threadIdx.x, b = blockIdx.x;
    int idx = b * 1024 + t;
    int v = (idx < NN) ? g_cnt[idx] : 0;
    sh[t] = v; __syncthreads();
    for (int s = 1; s < 1024; s <<= 1) {
        int add = (t >= s) ? sh[t - s] : 0;
        __syncthreads();
        sh[t] += add;
        __syncthreads();
    }
    g_rowtmp[idx] = sh[t];
    if (t == 1023) g_bsum[b] = sh[t];
}
// scan phase 2+3 fused: each block redundantly prefixes bsum then applies
__global__ void k_scan23() {
    __shared__ int off;
    int t = threadIdx.x, b = blockIdx.x;
    if (t == 0) {
        int acc = 0;
        for (int i = 0; i < b; i++) acc += g_bsum[i];
        off = acc;
    }
    __syncthreads();
    int idx = b * 1024 + t;
    if (idx < NN) g_rowoff[idx + 1] = g_rowtmp[idx] + off;
    if (idx == 0) g_rowoff[0] = 0;
}

// scatter with fused norm (identical arithmetic to old k_norm) + degf snapshot
__global__ void k_scatter(const int* ei, const float* ew) {
    int e = blockIdx.x * blockDim.x + threadIdx.x;
    if (e < NE) {
        int r = ei[e];
        double d = g_degd[r];
        if (d < 0.5) d += 1.0;
        float w = (float)((double)ew[e] / d);
        int pos = g_rowoff[r] + atomicAdd(&g_cur[r], 1);
        g_csre[pos] = make_int2(ei[NE + e], __float_as_int(w));
    }
    if (e < NN) g_degf[e] = (float)g_degd[e];
}

// canonicalize each CSR row: sort by (col, weight-bits) — FROZEN comparator.
// Shared-staged: 128 rows/block; fallback to global path if span exceeds cap.
#define RS_ROWS 128
#define RS_CAP 3072
__global__ void k_rowsort() {
    __shared__ int2 buf[RS_CAP];
    int t = threadIdx.x;            // 128 threads
    int r0 = blockIdx.x * RS_ROWS;
    int r1 = r0 + RS_ROWS; if (r1 > NN) r1 = NN;
    if (r0 >= NN) return;
    int base = g_rowoff[r0], end = g_rowoff[r1];
    int span = end - base;
    if (span <= RS_CAP) {
        for (int i = t; i < span; i += 128) buf[i] = g_csre[base + i];
        __syncthreads();
        int r = r0 + t;
        if (r < NN && t < RS_ROWS) {
            int j0 = g_rowoff[r] - base, j1 = g_rowoff[r + 1] - base;
            for (int i = j0 + 1; i < j1; i++) {
                int2 e = buf[i];
                int j = i - 1;
                while (j >= j0) {
                    int2 ej = buf[j];
                    if (ej.x > e.x || (ej.x == e.x && (unsigned)ej.y > (unsigned)e.y)) {
                        buf[j + 1] = ej; j--;
                    } else break;
                }
                buf[j + 1] = e;
            }
        }
        __syncthreads();
        for (int i = t; i < span; i += 128) g_csre[base + i] = buf[i];
    } else {
        int r = r0 + t;
        if (r < NN && t < RS_ROWS) {
            int j0 = g_rowoff[r], j1 = g_rowoff[r + 1];
            for (int i = j0 + 1; i < j1; i++) {
                int2 e = g_csre[i];
                int j = i - 1;
                while (j >= j0) {
                    int2 ej = g_csre[j];
                    if (ej.x > e.x || (ej.x == e.x && (unsigned)ej.y > (unsigned)e.y)) {
                        g_csre[j + 1] = ej; j--;
                    } else break;
                }
                g_csre[j + 1] = e;
            }
        }
    }
}

// embedding gather (fp32) + per-channel sum/sumsq (fp64 accumulate)
__global__ void k_embed(const int* x, const float* tab) {
    int c = threadIdx.x & 63;
    int rbase = blockIdx.x * 4 + (threadIdx.x >> 6);
    double s = 0.0, s2 = 0.0;
    for (int r = rbase; r < NN; r += gridDim.x * 4) {
        float v = tab[x[r] * 64 + c];
        g_E[r * 64 + c] = v;
        double vd = (double)v;
        s += vd; s2 += vd * vd;
    }
    atomicAdd(&g_d[D_EMB + c], s);
    atomicAdd(&g_d[D_EMB + 64 + c], s2);
}

// node Linear fp32 with inlined GN affine: out = relu( f(in)*W + b )
__global__ void k_lin(const float* in, int ldin, const double* sums,
                      const float* gw, const float* gb, const float* gm,
                      int prerelu, const float* W, const float* bias, double invN) {
    __shared__ float Xs[64][65];
    __shared__ float Ws[64][64];
    __shared__ float as_[64], cs_[64], bs_[64];
    int tid = threadIdx.x;
    for (int i = tid; i < 4096; i += 256) Ws[i >> 6][i & 63] = W[i];
    if (tid < 64) {
        affine_pair(sums, gw, gb, gm, 64, invN, tid, &as_[tid], &cs_[tid]);
        bs_[tid] = bias[tid];
    }
    __syncthreads();
    int r0 = blockIdx.x * 64;
    for (int i = tid; i < 4096; i += 256) {
        int r = i >> 6, c = i & 63;
        int gr = r0 + r;
        float v = 0.f;
        if (gr < NN) {
            v = fmaf(as_[c], in[gr * ldin + c], cs_[c]);
            if (prerelu) v = fmaxf(v, 0.f);
        }
        Xs[r][c] = v;
    }
    __syncthreads();
    int c = (tid & 15) * 4, rr = tid >> 4;
    float acc[4][4] = {};
    for (int k = 0; k < 64; k++) {
        float4 wv = *(const float4*)&Ws[k][c];
        #pragma unroll
        for (int i = 0; i < 4; i++) {
            float xv = Xs[rr + 16 * i][k];
            acc[i][0] = fmaf(xv, wv.x, acc[i][0]);
            acc[i][1] = fmaf(xv, wv.y, acc[i][1]);
            acc[i][2] = fmaf(xv, wv.z, acc[i][2]);
            acc[i][3] = fmaf(xv, wv.w, acc[i][3]);
        }
    }
    for (int i = 0; i < 4; i++) {
        int gr = r0 + rr + 16 * i;
        if (gr < NN) {
            float4 o;
            o.x = fmaxf(acc[i][0] + bs_[c + 0], 0.f);
            o.y = fmaxf(acc[i][1] + bs_[c + 1], 0.f);
            o.z = fmaxf(acc[i][2] + bs_[c + 2], 0.f);
            o.w = fmaxf(acc[i][3] + bs_[c + 3], 0.f);
            *(float4*)&g_hlin[gr * 64 + c] = o;
        }
    }
}

// CSR gather-SpMM fp32 (FROZEN row compute) + fused GN channel stats (fp64)
__global__ void k_spmm_csr(int coloff, double* sL, double* sG) {
    __shared__ double sh[128];            // [0:64] sum, [64:128] sumsq
    int t = threadIdx.x, lane = t & 31, wid = t >> 5;
    if (t < 128) sh[t] = 0.0;
    __syncthreads();
    int w0 = blockIdx.x * 8 + wid;
    int stride = gridDim.x * 8;
    double s0 = 0.0, s1 = 0.0, q0 = 0.0, q1 = 0.0;
    for (int w = w0; w < NN; w += stride) {
        int j0 = g_rowoff[w], j1 = g_rowoff[w + 1];
        float a0 = 0.f, a1 = 0.f;
        for (int j = j0; j < j1; j++) {
            int2 e = g_csre[j];
            float wt = __int_as_float(e.y);
            float2 v = *(const float2*)&g_hlin[e.x * 64 + lane * 2];
            a0 = fmaf(wt, v.x, a0);
            a1 = fmaf(wt, v.y, a1);
        }
        float2 o = { a0, a1 };
        *(float2*)&g_hcat[w * 192 + coloff + lane * 2] = o;
        double d0 = (double)a0, d1 = (double)a1;
        s0 += d0; s1 += d1; q0 += d0 * d0; q1 += d1 * d1;
    }
    atomicAdd(&sh[lane * 2 + 0], s0);
    atomicAdd(&sh[lane * 2 + 1], s1);
    atomicAdd(&sh[64 + lane * 2 + 0], q0);
    atomicAdd(&sh[64 + lane * 2 + 1], q1);
    __syncthreads();
    if (t < 64) {
        double ssum = sh[t], sq = sh[64 + t];
        atomicAdd(&sG[coloff + t], ssum);
        atomicAdd(&sG[192 + coloff + t], sq);
        if (sL) {
            atomicAdd(&sL[t], ssum);
            atomicAdd(&sL[64 + t], sq);
        }
    }
}

// s = gn(hcat) @ sW + sb, softmax (FROZEN g_ssmf realization); fused fp64
// partials (colsum, ss, den) + merged poolout partials — unchanged from R11.
__global__ void k_soft(const float* sW, const float* sb, const double* sums,
                       const float* glw, const float* glb, const float* glm,
                       double invN) {
    __shared__ float H[32][193];
    __shared__ float Ws[3072];
    __shared__ float Sm[32][17];
    __shared__ float sbs[16];
    __shared__ float af[192], cf[192];
    int t = threadIdx.x;
    for (int i = t; i < 3072; i += 256) Ws[i] = sW[i];
    if (t < 16) sbs[t] = sb[t];
    if (t < 192) affine_pair(sums, glw, glb, glm, 192, invN, t, &af[t], &cf[t]);
    int a_ = t >> 4, b_ = t & 15;
    int kp = t & 15, fbp = (t >> 4) * 12;
    double ss_acc = 0.0, col_acc = 0.0, den_acc = 0.0;
    float po[12];
    #pragma unroll
    for (int j = 0; j < 12; j++) po[j] = 0.f;
    for (int tile = blockIdx.x; tile < 1563; tile += gridDim.x) {
        int n0 = tile * 32;
        __syncthreads();
        for (int i = t; i < 32 * 192; i += 256) {
            int r = i / 192, f = i - r * 192;
            int gr = n0 + r;
            H[r][f] = (gr < NN) ? fmaf(af[f], g_hcat[gr * 192 + f], cf[f]) : 0.f;
        }
        __syncthreads();
        #pragma unroll
        for (int p = 0; p < 2; p++) {
            int i = a_ + 16 * p;
            float acc = 0.f;
            for (int f = 0; f < 192; f++) acc = fmaf(H[i][f], Ws[f * 16 + b_], acc);
            Sm[i][b_] = acc + sbs[b_];
        }
        __syncthreads();
        if (t < 32) {
            int gr = n0 + t;
            if (gr < NN) {
                float mx = -1e30f;
                #pragma unroll
                for (int j = 0; j < 16; j++) mx = fmaxf(mx, Sm[t][j]);
                float ev[16]; float s = 0.f;
                #pragma unroll
                for (int j = 0; j < 16; j++) { ev[j] = expf(Sm[t][j] - mx); s += ev[j]; }
                float inv = 1.f / s;
                float sq = 0.f;
                #pragma unroll
                for (int j = 0; j < 16; j++) {
                    float v = ev[j] * inv;
                    Sm[t][j] = v;
                    g_ssmf[gr * 16 + j] = v;
                    sq += v * v;
                }
                den_acc += (double)(g_degf[gr] * sq);
            } else {
                #pragma unroll
                for (int j = 0; j < 16; j++) Sm[t][j] = 0.f;
            }
        }
        __syncthreads();
        {
            float s = 0.f;
            #pragma unroll
            for (int i = 0; i < 32; i++) s += Sm[i][a_] * Sm[i][b_];
            ss_acc += (double)s;
        }
        if (t < 16) {
            float s = 0.f;
            #pragma unroll
            for (int i = 0; i < 32; i++) s += Sm[i][t];
            col_acc += (double)s;
        }
        #pragma unroll 4
        for (int i = 0; i < 32; i++) {
            float sv = Sm[i][kp];
            #pragma unroll
            for (int j = 0; j < 12; j++) po[j] = fmaf(sv, H[i][fbp + j], po[j]);
        }
    }
    atomicAdd(&g_d[D_SS + t], ss_acc);
    if (t < 16) atomicAdd(&g_d[D_COLSUM + t], col_acc);
    if (t < 32) atomicAdd(&g_d[D_DEN], den_acc);
    for (int j = 0; j < 12; j++)
        atomicAdd(&g_d[D_OUT + kp * 192 + fbp + j], (double)po[j]);
}

// mincut numerator: sum_e w[e] * <ssm[row], ssm[col]>  (fp32 dot, fp64 reduce)
__global__ void k_num(const int* ei, const float* ew) {
    float acc = 0.f;
    for (int e = blockIdx.x * blockDim.x + threadIdx.x; e < NE;
         e += gridDim.x * blockDim.x) {
        int r = ei[e], c = ei[NE + e];
        const float4* a = (const float4*)&g_ssmf[r * 16];
        const float4* b = (const float4*)&g_ssmf[c * 16];
        float d = 0.f;
        #pragma unroll
        for (int i = 0; i < 4; i++) {
            float4 av = a[i], bv = b[i];
            d += av.x * bv.x + av.y * bv.y + av.z * bv.z + av.w * bv.w;
        }
        acc = fmaf(ew[e], d, acc);
    }
    __shared__ double red[256];
    red[threadIdx.x] = (double)acc; __syncthreads();
    for (int s = 128; s > 0; s >>= 1) {
        if (threadIdx.x < s) red[threadIdx.x] += red[threadIdx.x + s];
        __syncthreads();
    }
    if (threadIdx.x == 0) atomicAdd(&g_d[D_NUM], red[0]);
}

// ======= sort keys: FROZEN per-(k,m) realization; 4 subgraphs per block =======
#define S2CH 512
__global__ void k_sub2v4(const float* SA) {
    __shared__ float sss[S2CH * 17];
    __shared__ float sa[4][S2CH];
    __shared__ float lr[4][16][17];
    int t = threadIdx.x;
    int k = t >> 4, lane = t & 15;
    float cs = (float)g_d[D_COLSUM + k];
    if (cs < 1e-12f) cs = 1e-12f;
    const float* sp0 = SA + (size_t)(blockIdx.x +   0) * NN;
    const float* sp1 = SA + (size_t)(blockIdx.x +  64) * NN;
    const float* sp2 = SA + (size_t)(blockIdx.x + 128) * NN;
    const float* sp3 = SA + (size_t)(blockIdx.x + 192) * NN;
    float acc0 = 0.f, acc1 = 0.f, acc2 = 0.f, acc3 = 0.f;
    for (int n0 = 0; n0 < NN; n0 += S2CH) {
        int span = NN - n0; if (span > S2CH) span = S2CH;
        __syncthreads();
        for (int i = t; i < span * 16; i += 256) {
            int n2 = i >> 4, kk = i & 15;
            sss[n2 * 17 + kk] = g_ssmf[(n0 + n2) * 16 + kk];
        }
        for (int i = t; i < span; i += 256) {
            sa[0][i] = sp0[n0 + i]; sa[1][i] = sp1[n0 + i];
            sa[2][i] = sp2[n0 + i]; sa[3][i] = sp3[n0 + i];
        }
        __syncthreads();
        for (int n2 = lane; n2 < span; n2 += 16) {
            float sv = sss[n2 * 17 + k];
            float tv = sv / cs;
            acc0 = fmaf(tv, sa[0][n2], acc0);
            acc1 = fmaf(tv, sa[1][n2], acc1);
            acc2 = fmaf(tv, sa[2][n2], acc2);
            acc3 = fmaf(tv, sa[3][n2], acc3);
        }
    }
    lr[0][k][lane] = acc0; lr[1][k][lane] = acc1;
    lr[2][k][lane] = acc2; lr[3][k][lane] = acc3;
    __syncthreads();
    for (int s = 8; s > 0; s >>= 1) {
        if (lane < s) {
            lr[0][k][lane] += lr[0][k][lane + s];
            lr[1][k][lane] += lr[1][k][lane + s];
            lr[2][k][lane] += lr[2][k][lane + s];
            lr[3][k][lane] += lr[3][k][lane + s];
        }
        __syncthreads();
    }
    if (lane == 0) {
        g_sub2f[k * 256 + blockIdx.x +   0] = lr[0][k][0];
        g_sub2f[k * 256 + blockIdx.x +  64] = lr[1][k][0];
        g_sub2f[k * 256 + blockIdx.x + 128] = lr[2][k][0];
        g_sub2f[k * 256 + blockIdx.x + 192] = lr[3][k][0];
    }
}

// per-subgraph sorted emb build + (block 0) losses — absorbs old k_fin
__global__ void k_embfin(float* dout) {
    __shared__ float rs[16];
    __shared__ int perm[16];
    int m = blockIdx.x, t = threadIdx.x;
    if (t < 16) rs[t] = g_sub2f[t * 256 + m];
    __syncthreads();
    if (t == 0) {
        int p[16];
        for (int i = 0; i < 16; i++) p[i] = i;
        for (int i = 1; i < 16; i++) {
            int key = p[i]; float kv = rs[key];
            int j = i - 1;
            while (j >= 0 && rs[p[j]] < kv) { p[j + 1] = p[j]; j--; }
            p[j + 1] = key;
        }
        for (int i = 0; i < 16; i++) perm[i] = p[i];
    }
    __syncthreads();
    for (int idx = t; idx < 3088; idx += 256) {
        int j = idx / 193, f = idx - j * 193;
        int pk = perm[j];
        g_emb[m * 3088 + idx] = (f < 192) ? (float)g_d[D_OUT + pk * 192 + f] : rs[pk];
    }
    if (blockIdx.x == 0) {
        __shared__ double red[256];
        __shared__ double fro;
        double v = g_d[D_SS + t];
        red[t] = v * v; __syncthreads();
        for (int s = 128; s > 0; s >>= 1) { if (t < s) red[t] += red[t + s]; __syncthreads(); }
        if (t == 0) fro = sqrt(red[0]);
        __syncthreads();
        double d = v / fro - (((t >> 4) == (t & 15)) ? 0.25 : 0.0);
        red[t] = d * d; __syncthreads();
        for (int s = 128; s > 0; s >>= 1) { if (t < s) red[t] += red[t + s]; __syncthreads(); }
        if (t == 0) {
            dout[16385] = (float)sqrt(red[0]);
            dout[16384] = (float)(-(g_d[D_NUM] / g_d[D_DEN]));
        }
    }
}

// MLP layer 1: 256x3088 @ 3088x128 fp32, split-K=16 with fp32 atomic accumulate
__global__ void k_mlp1(const float* W1) {
    int b = blockIdx.x;
    int rt = b & 7; b >>= 3; int ct = b & 1; int ks = b >> 1;
    int r0 = rt * 32, c0 = ct * 64, k0 = ks * 193;
    __shared__ float As[32][33];
    __shared__ float Bs[32][64];
    int t = threadIdx.x;
    int c = (t & 15) * 4, rr = (t >> 4) * 2;
    float acc[2][4] = {};
    for (int kk = 0; kk < 193; kk += 32) {
        int kc = 193 - kk; if (kc > 32) kc = 32;
        for (int i = t; i < 32 * 32; i += 256) {
            int r = i >> 5, kx = i & 31;
            As[r][kx] = (kx < kc) ? g_emb[(r0 + r) * 3088 + k0 + kk + kx] : 0.f;
        }
        for (int i = t; i < 32 * 64; i += 256) {
            int kx = i >> 6, cc = i & 63;
            Bs[kx][cc] = (kx < kc) ? W1[(k0 + kk + kx) * 128 + c0 + cc] : 0.f;
        }
        __syncthreads();
        #pragma unroll 8
        for (int kx = 0; kx < 32; kx++) {
            float4 bv = *(const float4*)&Bs[kx][c];
            float a0 = As[rr][kx], a1 = As[rr + 1][kx];
            acc[0][0] = fmaf(a0, bv.x, acc[0][0]); acc[0][1] = fmaf(a0, bv.y, acc[0][1]);
            acc[0][2] = fmaf(a0, bv.z, acc[0][2]); acc[0][3] = fmaf(a0, bv.w, acc[0][3]);
            acc[1][0] = fmaf(a1, bv.x, acc[1][0]); acc[1][1] = fmaf(a1, bv.y, acc[1][1]);
            acc[1][2] = fmaf(a1, bv.z, acc[1][2]); acc[1][3] = fmaf(a1, bv.w, acc[1][3]);
        }
        __syncthreads();
    }
    for (int i = 0; i < 2; i++)
        for (int j = 0; j < 4; j++)
            atomicAdd(&g_h1pre[(r0 + rr + i) * 128 + c0 + c + j], acc[i][j]);
}

// MLP tail: bias+relu then layers 2,3,4 in one kernel (row-local, deterministic)
__global__ void k_mlptail(const float* b1, const float* W2, const float* b2,
                          const float* W3, const float* b3,
                          const float* W4, const float* b4, float* out) {
    __shared__ float Hs[32][129];
    __shared__ float Bs[32][128];
    int t = threadIdx.x;
    int r0 = blockIdx.x * 32;
    for (int i = t; i < 32 * 128; i += 256) {
        int r = i >> 7, c = i & 127;
        Hs[r][c] = fmaxf(g_h1pre[(r0 + r) * 128 + c] + b1[c], 0.f);
    }
    __syncthreads();
    int c8 = (t & 15) * 8, rr = (t >> 4) * 2;
    for (int layer = 0; layer < 2; layer++) {
        const float* W = layer ? W3 : W2;
        const float* bb = layer ? b3 : b2;
        float acc[2][8] = {};
        for (int k0 = 0; k0 < 128; k0 += 32) {
            for (int i = t; i < 32 * 128; i += 256) {
                int kx = i >> 7, cc = i & 127;
                Bs[kx][cc] = W[(k0 + kx) * 128 + cc];
            }
            __syncthreads();
            for (int kx = 0; kx < 32; kx++) {
                float h0 = Hs[rr][k0 + kx], h1v = Hs[rr + 1][k0 + kx];
                #pragma unroll
                for (int j = 0; j < 8; j++) {
                    float w = Bs[kx][c8 + j];
                    acc[0][j] = fmaf(h0, w, acc[0][j]);
                    acc[1][j] = fmaf(h1v, w, acc[1][j]);
                }
            }
            __syncthreads();
        }
        #pragma unroll
        for (int i = 0; i < 2; i++)
            #pragma unroll
            for (int j = 0; j < 8; j++)
                Hs[rr + i][c8 + j] = fmaxf(acc[i][j] + bb[c8 + j], 0.f);
        __syncthreads();
    }
    {   // layer 4: 128 -> 64
        int c4 = (t & 15) * 4;
        float acc[2][4] = {};
        for (int k0 = 0; k0 < 128; k0 += 32) {
            for (int i = t; i < 32 * 64; i += 256) {
                int kx = i >> 6, cc = i & 63;
                Bs[kx][cc] = W4[(k0 + kx) * 64 + cc];
            }
            __syncthreads();
            for (int kx = 0; kx < 32; kx++) {
                float h0 = Hs[rr][k0 + kx], h1v = Hs[rr + 1][k0 + kx];
                #pragma unroll
                for (int j = 0; j < 4; j++) {
                    float w = Bs[kx][c4 + j];
                    acc[0][j] = fmaf(h0, w, acc[0][j]);
                    acc[1][j] = fmaf(h1v, w, acc[1][j]);
                }
            }
            __syncthreads();
        }
        #pragma unroll
        for (int i = 0; i < 2; i++)
            #pragma unroll
            for (int j = 0; j < 4; j++)
                out[(r0 + rr + i) * 64 + c4 + j] = acc[i][j] + b4[c4 + j];
    }
}

// ---------------- launch ----------------
extern "C" void kernel_launch(void* const* d_in, const int* in_sizes, int n_in,
                              void* d_out, int out_size) {
    const int*   x    = (const int*)d_in[0];
    const int*   ei   = (const int*)d_in[1];
    const float* ew   = (const float*)d_in[2];
    const float* SA   = (const float*)d_in[4];
    const float* tab  = (const float*)d_in[5];
    const float* egw  = (const float*)d_in[6];
    const float* egb  = (const float*)d_in[7];
    const float* egm  = (const float*)d_in[8];
    const float* cW   = (const float*)d_in[9];
    const float* cB   = (const float*)d_in[10];
    const float* gnw  = (const float*)d_in[11];
    const float* gnb  = (const float*)d_in[12];
    const float* gnm  = (const float*)d_in[13];
    const float* glw  = (const float*)d_in[14];
    const float* glb  = (const float*)d_in[15];
    const float* glm  = (const float*)d_in[16];
    const float* sW   = (const float*)d_in[17];
    const float* sb   = (const float*)d_in[18];
    const float* pW1  = (const float*)d_in[19];
    const float* pb1  = (const float*)d_in[20];
    const float* pW2  = (const float*)d_in[21];
    const float* pb2  = (const float*)d_in[22];
    const float* pW3  = (const float*)d_in[23];
    const float* pb3  = (const float*)d_in[24];
    const float* pW4  = (const float*)d_in[25];
    const float* pb4  = (const float*)d_in[26];
    float* out = (float*)d_out;

    void *pv;
    float *E_p, *hcat_p;
    double *d_p;
    cudaGetSymbolAddress(&pv, g_E);    E_p    = (float*)pv;
    cudaGetSymbolAddress(&pv, g_hcat); hcat_p = (float*)pv;
    cudaGetSymbolAddress(&pv, g_d);    d_p    = (double*)pv;

    const double invN = 1.0 / (double)NN;

    k_init<<<196, 256>>>();
    k_deg<<<3125, 256>>>(ei, ew);
    k_scan1<<<49, 1024>>>();
    k_scan23<<<49, 1024>>>();
    k_scatter<<<3125, 256>>>(ei, ew);
    k_rowsort<<<391, 128>>>();
    k_embed<<<256, 256>>>(x, tab);

    // layer 0
    k_lin<<<782, 256>>>(E_p, 64, d_p + D_EMB, egw, egb, egm, 0, cW, cB, invN);
    k_spmm_csr<<<400, 256>>>(0, d_p + D_G0, d_p + D_GL);
    // layer 1
    k_lin<<<782, 256>>>(hcat_p, 192, d_p + D_G0, gnw, gnb, gnm, 1, cW + 4096, cB + 64, invN);
    k_spmm_csr<<<400, 256>>>(64, d_p + D_G1, d_p + D_GL);
    // layer 2
    k_lin<<<782, 256>>>(hcat_p + 64, 192, d_p + D_G1, gnw + 64, gnb + 64, gnm + 64,
                        1, cW + 8192, cB + 128, invN);
    k_spmm_csr<<<400, 256>>>(128, (double*)0, d_p + D_GL);

    k_soft<<<256, 256>>>(sW, sb, d_p + D_GL, glw, glb, glm, invN);
    k_num<<<2048, 256>>>(ei, ew);
    k_sub2v4<<<64, 256>>>(SA);
    k_embfin<<<256, 256>>>(out);

    k_mlp1<<<256, 256>>>(pW1);
    k_mlptail<<<8, 256>>>(pb1, pW2, pb2, pW3, pb3, pW4, pb4, out);

    (void)in_sizes; (void)n_in; (void)out_size;
}

// round 13
// speedup vs baseline: 1.5480x; 1.5480x over previous
#include <cuda_runtime.h>
#include <math.h>

#define NN 50000
#define NE 800000
#define EPSV 1e-5

// ---------------- scratch (__device__ globals; no runtime alloc) ----------------
__device__ double g_degd[NN];          // fp64 degree (deterministic to 1e-16)
__device__ float  g_degf[NN];          // fp32 snapshot for mincut_den
__device__ float  g_normw[NE];
__device__ float  g_E[NN * 64];
__device__ float  g_hlin[NN * 64];
__device__ float  g_hcat[NN * 192];
__device__ float  g_ssmf[NN * 16];     // fp32 ssm (feeds key kernel — FROZEN)
__device__ float  g_outf[16 * 192];
__device__ float  g_emb[256 * 3088];
__device__ float  g_h1pre[256 * 128];
__device__ float  g_sub2f[16 * 256];   // fp32 sort keys (winning realization — FROZEN)

// CSR structures (built once per launch; rows canonically sorted -> deterministic)
__device__ int    g_cnt[NN];
__device__ int    g_cur[NN];
__device__ int    g_rowoff[NN + 1];
__device__ int2   g_csre[NE];          // (col, weight-bits)
__device__ int    g_rowtmp[50176];
__device__ int    g_bsum[64];

// fp64 accumulator zone (memset to 0 once per launch)
#define D_EMB    0      // 128
#define D_G0     128    // 128
#define D_G1     256    // 128
#define D_GL     384    // 384
#define D_COLSUM 768    // 16
#define D_SS     784    // 256
#define D_NUM    1040   // 1
#define D_DEN    1041   // 1
#define D_OUT    1048   // 3072
#define D_TOTAL  4120
__device__ double g_d[D_TOTAL];

// GraphNorm affine from fp64 stats (identical math across rounds)
__device__ __forceinline__ void affine_pair(const double* sums, const float* w,
        const float* b, const float* ms, int C, double invN, int c,
        float* a_out, float* c_out) {
    double mu = sums[c] * invN;
    double ex2 = sums[C + c] * invN;
    double m = (double)ms[c];
    double var = ex2 - 2.0 * m * mu * mu + m * m * mu * mu;
    double a = (double)w[c] / sqrt(var + EPSV);
    *a_out = (float)a;
    *c_out = (float)((double)b[c] - a * m * mu);
}

// ---------------- kernels ----------------

__global__ void k_deg(const int* ei, const float* ew) {
    int e = blockIdx.x * blockDim.x + threadIdx.x;
    if (e < NE) {
        atomicAdd(&g_degd[ei[e]], (double)ew[e]);
        atomicAdd(&g_cnt[ei[e]], 1);
    }
}

__global__ void k_norm(const int* ei, const float* ew) {
    int e = blockIdx.x * blockDim.x + threadIdx.x;
    if (e < NE) {
        double d = g_degd[ei[e]];
        if (d < 0.5) d += 1.0;
        g_normw[e] = (float)((double)ew[e] / d);
    }
    if (e < NN) g_degf[e] = (float)g_degd[e];
}

// 3-phase deterministic int scan
__global__ void k_scan1() {
    __shared__ int sh[1024];
    int t = threadIdx.x, b = blockIdx.x;
    int idx = b * 1024 + t;
    int v = (idx < NN) ? g_cnt[idx] : 0;
    sh[t] = v; __syncthreads();
    for (int s = 1; s < 1024; s <<= 1) {
        int add = (t >= s) ? sh[t - s] : 0;
        __syncthreads();
        sh[t] += add;
        __syncthreads();
    }
    g_rowtmp[idx] = sh[t];
    if (t == 1023) g_bsum[b] = sh[t];
}
__global__ void k_scan2() {
    if (threadIdx.x == 0) {
        int acc = 0;
        for (int i = 0; i < 49; i++) { int v = g_bsum[i]; g_bsum[i] = acc; acc += v; }
    }
}
__global__ void k_scan3() {
    int t = threadIdx.x, b = blockIdx.x;
    int idx = b * 1024 + t;
    if (idx < NN) g_rowoff[idx + 1] = g_rowtmp[idx] + g_bsum[b];
    if (idx == 0) g_rowoff[0] = 0;
}

__global__ void k_scatter(const int* ei) {
    int e = blockIdx.x * blockDim.x + threadIdx.x;
    if (e < NE) {
        int r = ei[e];
        int pos = g_rowoff[r] + atomicAdd(&g_cur[r], 1);
        g_csre[pos] = make_int2(ei[NE + e], __float_as_int(g_normw[e]));
    }
}

// canonicalize each CSR row: insertion sort by (col, weight-bits) — FROZEN comparator
__global__ void k_rowsort() {
    int r = blockIdx.x * blockDim.x + threadIdx.x;
    if (r >= NN) return;
    int j0 = g_rowoff[r], j1 = g_rowoff[r + 1];
    for (int i = j0 + 1; i < j1; i++) {
        int2 e = g_csre[i];
        int j = i - 1;
        while (j >= j0) {
            int2 ej = g_csre[j];
            if (ej.x > e.x || (ej.x == e.x && (unsigned)ej.y > (unsigned)e.y)) {
                g_csre[j + 1] = ej; j--;
            } else break;
        }
        g_csre[j + 1] = e;
    }
}

// embedding gather (fp32) + per-channel sum/sumsq (fp64 accumulate)
__global__ void k_embed(const int* x, const float* tab) {
    int c = threadIdx.x & 63;
    int rbase = blockIdx.x * 4 + (threadIdx.x >> 6);
    double s = 0.0, s2 = 0.0;
    for (int r = rbase; r < NN; r += gridDim.x * 4) {
        float v = tab[x[r] * 64 + c];
        g_E[r * 64 + c] = v;
        double vd = (double)v;
        s += vd; s2 += vd * vd;
    }
    atomicAdd(&g_d[D_EMB + c], s);
    atomicAdd(&g_d[D_EMB + 64 + c], s2);
}

// node Linear fp32 with inlined GN affine: out = relu( f(in)*W + b )
__global__ void k_lin(const float* in, int ldin, const double* sums,
                      const float* gw, const float* gb, const float* gm,
                      int prerelu, const float* W, const float* bias, double invN) {
    __shared__ float Xs[64][65];
    __shared__ float Ws[64][64];
    __shared__ float as_[64], cs_[64], bs_[64];
    int tid = threadIdx.x;
    for (int i = tid; i < 4096; i += 256) Ws[i >> 6][i & 63] = W[i];
    if (tid < 64) {
        affine_pair(sums, gw, gb, gm, 64, invN, tid, &as_[tid], &cs_[tid]);
        bs_[tid] = bias[tid];
    }
    __syncthreads();
    int r0 = blockIdx.x * 64;
    for (int i = tid; i < 4096; i += 256) {
        int r = i >> 6, c = i & 63;
        int gr = r0 + r;
        float v = 0.f;
        if (gr < NN) {
            v = fmaf(as_[c], in[gr * ldin + c], cs_[c]);
            if (prerelu) v = fmaxf(v, 0.f);
        }
        Xs[r][c] = v;
    }
    __syncthreads();
    int c = (tid & 15) * 4, rr = tid >> 4;
    float acc[4][4] = {};
    for (int k = 0; k < 64; k++) {
        float4 wv = *(const float4*)&Ws[k][c];
        #pragma unroll
        for (int i = 0; i < 4; i++) {
            float xv = Xs[rr + 16 * i][k];
            acc[i][0] = fmaf(xv, wv.x, acc[i][0]);
            acc[i][1] = fmaf(xv, wv.y, acc[i][1]);
            acc[i][2] = fmaf(xv, wv.z, acc[i][2]);
            acc[i][3] = fmaf(xv, wv.w, acc[i][3]);
        }
    }
    for (int i = 0; i < 4; i++) {
        int gr = r0 + rr + 16 * i;
        if (gr < NN) {
            float4 o;
            o.x = fmaxf(acc[i][0] + bs_[c + 0], 0.f);
            o.y = fmaxf(acc[i][1] + bs_[c + 1], 0.f);
            o.z = fmaxf(acc[i][2] + bs_[c + 2], 0.f);
            o.w = fmaxf(acc[i][3] + bs_[c + 3], 0.f);
            *(float4*)&g_hlin[gr * 64 + c] = o;
        }
    }
}

// CSR gather-SpMM fp32 (FROZEN row compute) + fused GN channel stats (fp64)
__global__ void k_spmm_csr(int coloff, double* sL, double* sG) {
    __shared__ double sh[128];            // [0:64] sum, [64:128] sumsq
    int t = threadIdx.x, lane = t & 31, wid = t >> 5;
    if (t < 128) sh[t] = 0.0;
    __syncthreads();
    int w0 = blockIdx.x * 8 + wid;
    int stride = gridDim.x * 8;
    double s0 = 0.0, s1 = 0.0, q0 = 0.0, q1 = 0.0;
    for (int w = w0; w < NN; w += stride) {
        int j0 = g_rowoff[w], j1 = g_rowoff[w + 1];
        float a0 = 0.f, a1 = 0.f;
        for (int j = j0; j < j1; j++) {
            int2 e = g_csre[j];
            float wt = __int_as_float(e.y);
            float2 v = *(const float2*)&g_hlin[e.x * 64 + lane * 2];
            a0 = fmaf(wt, v.x, a0);
            a1 = fmaf(wt, v.y, a1);
        }
        float2 o = { a0, a1 };
        *(float2*)&g_hcat[w * 192 + coloff + lane * 2] = o;
        double d0 = (double)a0, d1 = (double)a1;
        s0 += d0; s1 += d1; q0 += d0 * d0; q1 += d1 * d1;
    }
    atomicAdd(&sh[lane * 2 + 0], s0);
    atomicAdd(&sh[lane * 2 + 1], s1);
    atomicAdd(&sh[64 + lane * 2 + 0], q0);
    atomicAdd(&sh[64 + lane * 2 + 1], q1);
    __syncthreads();
    if (t < 64) {
        double ssum = sh[t], sq = sh[64 + t];
        atomicAdd(&sG[coloff + t], ssum);
        atomicAdd(&sG[192 + coloff + t], sq);
        if (sL) {
            atomicAdd(&sL[t], ssum);
            atomicAdd(&sL[64 + t], sq);
        }
    }
}

// s = gn(hcat) @ sW + sb, softmax (FROZEN g_ssmf realization); fused fp64
// partials (colsum, ss, den) + merged poolout partials.
__global__ void k_soft(const float* sW, const float* sb, const double* sums,
                       const float* glw, const float* glb, const float* glm,
                       double invN) {
    __shared__ float H[32][193];
    __shared__ float Ws[3072];
    __shared__ float Sm[32][17];
    __shared__ float sbs[16];
    __shared__ float af[192], cf[192];
    int t = threadIdx.x;
    for (int i = t; i < 3072; i += 256) Ws[i] = sW[i];
    if (t < 16) sbs[t] = sb[t];
    if (t < 192) affine_pair(sums, glw, glb, glm, 192, invN, t, &af[t], &cf[t]);
    int a_ = t >> 4, b_ = t & 15;
    int kp = t & 15, fbp = (t >> 4) * 12;
    double ss_acc = 0.0, col_acc = 0.0, den_acc = 0.0;
    float po[12];
    #pragma unroll
    for (int j = 0; j < 12; j++) po[j] = 0.f;
    for (int tile = blockIdx.x; tile < 1563; tile += gridDim.x) {
        int n0 = tile * 32;
        __syncthreads();
        for (int i = t; i < 32 * 192; i += 256) {
            int r = i / 192, f = i - r * 192;
            int gr = n0 + r;
            H[r][f] = (gr < NN) ? fmaf(af[f], g_hcat[gr * 192 + f], cf[f]) : 0.f;
        }
        __syncthreads();
        #pragma unroll
        for (int p = 0; p < 2; p++) {
            int i = a_ + 16 * p;
            float acc = 0.f;
            for (int f = 0; f < 192; f++) acc = fmaf(H[i][f], Ws[f * 16 + b_], acc);
            Sm[i][b_] = acc + sbs[b_];
        }
        __syncthreads();
        if (t < 32) {
            int gr = n0 + t;
            if (gr < NN) {
                float mx = -1e30f;
                #pragma unroll
                for (int j = 0; j < 16; j++) mx = fmaxf(mx, Sm[t][j]);
                float ev[16]; float s = 0.f;
                #pragma unroll
                for (int j = 0; j < 16; j++) { ev[j] = expf(Sm[t][j] - mx); s += ev[j]; }
                float inv = 1.f / s;
                float sq = 0.f;
                #pragma unroll
                for (int j = 0; j < 16; j++) {
                    float v = ev[j] * inv;
                    Sm[t][j] = v;
                    g_ssmf[gr * 16 + j] = v;
                    sq += v * v;
                }
                den_acc += (double)(g_degf[gr] * sq);
            } else {
                #pragma unroll
                for (int j = 0; j < 16; j++) Sm[t][j] = 0.f;
            }
        }
        __syncthreads();
        {
            float s = 0.f;
            #pragma unroll
            for (int i = 0; i < 32; i++) s += Sm[i][a_] * Sm[i][b_];
            ss_acc += (double)s;
        }
        if (t < 16) {
            float s = 0.f;
            #pragma unroll
            for (int i = 0; i < 32; i++) s += Sm[i][t];
            col_acc += (double)s;
        }
        #pragma unroll 4
        for (int i = 0; i < 32; i++) {
            float sv = Sm[i][kp];
            #pragma unroll
            for (int j = 0; j < 12; j++) po[j] = fmaf(sv, H[i][fbp + j], po[j]);
        }
    }
    atomicAdd(&g_d[D_SS + t], ss_acc);
    if (t < 16) atomicAdd(&g_d[D_COLSUM + t], col_acc);
    if (t < 32) atomicAdd(&g_d[D_DEN], den_acc);
    for (int j = 0; j < 12; j++)
        atomicAdd(&g_d[D_OUT + kp * 192 + fbp + j], (double)po[j]);
}

// mincut numerator: sum_e w[e] * <ssm[row], ssm[col]>  (fp32 dot, fp64 reduce)
__global__ void k_num(const int* ei, const float* ew) {
    float acc = 0.f;
    for (int e = blockIdx.x * blockDim.x + threadIdx.x; e < NE;
         e += gridDim.x * blockDim.x) {
        int r = ei[e], c = ei[NE + e];
        const float4* a = (const float4*)&g_ssmf[r * 16];
        const float4* b = (const float4*)&g_ssmf[c * 16];
        float d = 0.f;
        #pragma unroll
        for (int i = 0; i < 4; i++) {
            float4 av = a[i], bv = b[i];
            d += av.x * bv.x + av.y * bv.y + av.z * bv.z + av.w * bv.w;
        }
        acc = fmaf(ew[e], d, acc);
    }
    __shared__ double red[256];
    red[threadIdx.x] = (double)acc; __syncthreads();
    for (int s = 128; s > 0; s >>= 1) {
        if (threadIdx.x < s) red[threadIdx.x] += red[threadIdx.x + s];
        __syncthreads();
    }
    if (threadIdx.x == 0) atomicAdd(&g_d[D_NUM], red[0]);
}

// ======= sort keys: FROZEN per-(k,m) realization; 2 subgraphs per block =======
#define S2CH 512
__global__ void k_sub2v2(const float* SA) {
    __shared__ float sss[S2CH * 17];
    __shared__ float sa0[S2CH], sa1[S2CH];
    __shared__ float lr[2][16][17];
    int t = threadIdx.x;
    int k = t >> 4, lane = t & 15;
    int m0 = blockIdx.x, m1 = blockIdx.x + 128;
    float cs = (float)g_d[D_COLSUM + k];
    if (cs < 1e-12f) cs = 1e-12f;
    const float* sA0 = SA + (size_t)m0 * NN;
    const float* sA1 = SA + (size_t)m1 * NN;
    float acc0 = 0.f, acc1 = 0.f;
    for (int n0 = 0; n0 < NN; n0 += S2CH) {
        int span = NN - n0; if (span > S2CH) span = S2CH;
        __syncthreads();
        for (int i = t; i < span * 16; i += 256) {
            int n2 = i >> 4, kk = i & 15;
            sss[n2 * 17 + kk] = g_ssmf[(n0 + n2) * 16 + kk];
        }
        for (int i = t; i < span; i += 256) { sa0[i] = sA0[n0 + i]; sa1[i] = sA1[n0 + i]; }
        __syncthreads();
        for (int n2 = lane; n2 < span; n2 += 16) {
            float sv = sss[n2 * 17 + k];
            float tv = sv / cs;
            acc0 = fmaf(tv, sa0[n2], acc0);
            acc1 = fmaf(tv, sa1[n2], acc1);
        }
    }
    lr[0][k][lane] = acc0; lr[1][k][lane] = acc1;
    __syncthreads();
    for (int s = 8; s > 0; s >>= 1) {
        if (lane < s) {
            lr[0][k][lane] += lr[0][k][lane + s];
            lr[1][k][lane] += lr[1][k][lane + s];
        }
        __syncthreads();
    }
    if (lane == 0) {
        g_sub2f[k * 256 + m0] = lr[0][k][0];
        g_sub2f[k * 256 + m1] = lr[1][k][0];
    }
}

// losses (fp64) + out conversion
__global__ void k_fin(float* dout) {
    int t = threadIdx.x;
    __shared__ double red[256];
    __shared__ double fro;
    for (int idx = t; idx < 3072; idx += 256)
        g_outf[idx] = (float)g_d[D_OUT + idx];
    double v = g_d[D_SS + t];
    red[t] = v * v; __syncthreads();
    for (int s = 128; s > 0; s >>= 1) { if (t < s) red[t] += red[t + s]; __syncthreads(); }
    if (t == 0) fro = sqrt(red[0]);
    __syncthreads();
    double d = v / fro - (((t >> 4) == (t & 15)) ? 0.25 : 0.0);
    red[t] = d * d; __syncthreads();
    for (int s = 128; s > 0; s >>= 1) { if (t < s) red[t] += red[t + s]; __syncthreads(); }
    if (t == 0) {
        dout[16385] = (float)sqrt(red[0]);
        dout[16384] = (float)(-(g_d[D_NUM] / g_d[D_DEN]));
    }
}

// per-subgraph: stable sort clusters by fp32 score desc, emit emb row (fp32)
__global__ void k_embbuild() {
    __shared__ float rs[16];
    __shared__ int perm[16];
    int m = blockIdx.x, t = threadIdx.x;
    if (t < 16) rs[t] = g_sub2f[t * 256 + m];
    __syncthreads();
    if (t == 0) {
        int p[16];
        for (int i = 0; i < 16; i++) p[i] = i;
        for (int i = 1; i < 16; i++) {
            int key = p[i]; float kv = rs[key];
            int j = i - 1;
            while (j >= 0 && rs[p[j]] < kv) { p[j + 1] = p[j]; j--; }
            p[j + 1] = key;
        }
        for (int i = 0; i < 16; i++) perm[i] = p[i];
    }
    __syncthreads();
    for (int idx = t; idx < 3088; idx += 256) {
        int j = idx / 193, f = idx - j * 193;
        int pk = perm[j];
        g_emb[m * 3088 + idx] = (f < 192) ? g_outf[pk * 192 + f] : rs[pk];
    }
}

// MLP layer 1: 256x3088 @ 3088x128 fp32, split-K=16 with fp32 atomic accumulate
__global__ void k_mlp1(const float* W1) {
    int b = blockIdx.x;
    int rt = b & 7; b >>= 3; int ct = b & 1; int ks = b >> 1;
    int r0 = rt * 32, c0 = ct * 64, k0 = ks * 193;
    __shared__ float As[32][33];
    __shared__ float Bs[32][64];
    int t = threadIdx.x;
    int c = (t & 15) * 4, rr = (t >> 4) * 2;
    float acc[2][4] = {};
    for (int kk = 0; kk < 193; kk += 32) {
        int kc = 193 - kk; if (kc > 32) kc = 32;
        for (int i = t; i < 32 * 32; i += 256) {
            int r = i >> 5, kx = i & 31;
            As[r][kx] = (kx < kc) ? g_emb[(r0 + r) * 3088 + k0 + kk + kx] : 0.f;
        }
        for (int i = t; i < 32 * 64; i += 256) {
            int kx = i >> 6, cc = i & 63;
            Bs[kx][cc] = (kx < kc) ? W1[(k0 + kk + kx) * 128 + c0 + cc] : 0.f;
        }
        __syncthreads();
        #pragma unroll 8
        for (int kx = 0; kx < 32; kx++) {
            float4 bv = *(const float4*)&Bs[kx][c];
            float a0 = As[rr][kx], a1 = As[rr + 1][kx];
            acc[0][0] = fmaf(a0, bv.x, acc[0][0]); acc[0][1] = fmaf(a0, bv.y, acc[0][1]);
            acc[0][2] = fmaf(a0, bv.z, acc[0][2]); acc[0][3] = fmaf(a0, bv.w, acc[0][3]);
            acc[1][0] = fmaf(a1, bv.x, acc[1][0]); acc[1][1] = fmaf(a1, bv.y, acc[1][1]);
            acc[1][2] = fmaf(a1, bv.z, acc[1][2]); acc[1][3] = fmaf(a1, bv.w, acc[1][3]);
        }
        __syncthreads();
    }
    for (int i = 0; i < 2; i++)
        for (int j = 0; j < 4; j++)
            atomicAdd(&g_h1pre[(r0 + rr + i) * 128 + c0 + c + j], acc[i][j]);
}

// MLP tail: bias+relu then layers 2,3,4 in one kernel (row-local, deterministic)
__global__ void k_mlptail(const float* b1, const float* W2, const float* b2,
                          const float* W3, const float* b3,
                          const float* W4, const float* b4, float* out) {
    __shared__ float Hs[32][129];
    __shared__ float Bs[32][128];
    int t = threadIdx.x;
    int r0 = blockIdx.x * 32;
    for (int i = t; i < 32 * 128; i += 256) {
        int r = i >> 7, c = i & 127;
        Hs[r][c] = fmaxf(g_h1pre[(r0 + r) * 128 + c] + b1[c], 0.f);
    }
    __syncthreads();
    int c8 = (t & 15) * 8, rr = (t >> 4) * 2;
    for (int layer = 0; layer < 2; layer++) {
        const float* W = layer ? W3 : W2;
        const float* bb = layer ? b3 : b2;
        float acc[2][8] = {};
        for (int k0 = 0; k0 < 128; k0 += 32) {
            for (int i = t; i < 32 * 128; i += 256) {
                int kx = i >> 7, cc = i & 127;
                Bs[kx][cc] = W[(k0 + kx) * 128 + cc];
            }
            __syncthreads();
            for (int kx = 0; kx < 32; kx++) {
                float h0 = Hs[rr][k0 + kx], h1v = Hs[rr + 1][k0 + kx];
                #pragma unroll
                for (int j = 0; j < 8; j++) {
                    float w = Bs[kx][c8 + j];
                    acc[0][j] = fmaf(h0, w, acc[0][j]);
                    acc[1][j] = fmaf(h1v, w, acc[1][j]);
                }
            }
            __syncthreads();
        }
        #pragma unroll
        for (int i = 0; i < 2; i++)
            #pragma unroll
            for (int j = 0; j < 8; j++)
                Hs[rr + i][c8 + j] = fmaxf(acc[i][j] + bb[c8 + j], 0.f);
        __syncthreads();
    }
    {   // layer 4: 128 -> 64
        int c4 = (t & 15) * 4;
        float acc[2][4] = {};
        for (int k0 = 0; k0 < 128; k0 += 32) {
            for (int i = t; i < 32 * 64; i += 256) {
                int kx = i >> 6, cc = i & 63;
                Bs[kx][cc] = W4[(k0 + kx) * 64 + cc];
            }
            __syncthreads();
            for (int kx = 0; kx < 32; kx++) {
                float h0 = Hs[rr][k0 + kx], h1v = Hs[rr + 1][k0 + kx];
                #pragma unroll
                for (int j = 0; j < 4; j++) {
                    float w = Bs[kx][c4 + j];
                    acc[0][j] = fmaf(h0, w, acc[0][j]);
                    acc[1][j] = fmaf(h1v, w, acc[1][j]);
                }
            }
            __syncthreads();
        }
        #pragma unroll
        for (int i = 0; i < 2; i++)
            #pragma unroll
            for (int j = 0; j < 4; j++)
                out[(r0 + rr + i) * 64 + c4 + j] = acc[i][j] + b4[c4 + j];
    }
}

// ---------------- launch ----------------
extern "C" void kernel_launch(void* const* d_in, const int* in_sizes, int n_in,
                              void* d_out, int out_size) {
    const int*   x    = (const int*)d_in[0];
    const int*   ei   = (const int*)d_in[1];
    const float* ew   = (const float*)d_in[2];
    const float* SA   = (const float*)d_in[4];
    const float* tab  = (const float*)d_in[5];
    const float* egw  = (const float*)d_in[6];
    const float* egb  = (const float*)d_in[7];
    const float* egm  = (const float*)d_in[8];
    const float* cW   = (const float*)d_in[9];
    const float* cB   = (const float*)d_in[10];
    const float* gnw  = (const float*)d_in[11];
    const float* gnb  = (const float*)d_in[12];
    const float* gnm  = (const float*)d_in[13];
    const float* glw  = (const float*)d_in[14];
    const float* glb  = (const float*)d_in[15];
    const float* glm  = (const float*)d_in[16];
    const float* sW   = (const float*)d_in[17];
    const float* sb   = (const float*)d_in[18];
    const float* pW1  = (const float*)d_in[19];
    const float* pb1  = (const float*)d_in[20];
    const float* pW2  = (const float*)d_in[21];
    const float* pb2  = (const float*)d_in[22];
    const float* pW3  = (const float*)d_in[23];
    const float* pb3  = (const float*)d_in[24];
    const float* pW4  = (const float*)d_in[25];
    const float* pb4  = (const float*)d_in[26];
    float* out = (float*)d_out;

    void *pv;
    float *E_p, *hcat_p, *h1pre_p;
    double *degd_p, *d_p;
    int *cnt_p, *cur_p;
    cudaGetSymbolAddress(&pv, g_degd);    degd_p  = (double*)pv;
    cudaGetSymbolAddress(&pv, g_E);       E_p     = (float*)pv;
    cudaGetSymbolAddress(&pv, g_hcat);    hcat_p  = (float*)pv;
    cudaGetSymbolAddress(&pv, g_h1pre);   h1pre_p = (float*)pv;
    cudaGetSymbolAddress(&pv, g_d);       d_p     = (double*)pv;
    cudaGetSymbolAddress(&pv, g_cnt);     cnt_p   = (int*)pv;
    cudaGetSymbolAddress(&pv, g_cur);     cur_p   = (int*)pv;

    cudaMemsetAsync(degd_p, 0, (size_t)NN * 8);
    cudaMemsetAsync(h1pre_p, 0, (size_t)256 * 128 * 4);
    cudaMemsetAsync(d_p, 0, (size_t)D_TOTAL * 8);
    cudaMemsetAsync(cnt_p, 0, (size_t)NN * 4);
    cudaMemsetAsync(cur_p, 0, (size_t)NN * 4);

    const double invN = 1.0 / (double)NN;

    k_deg<<<3125, 256>>>(ei, ew);
    k_norm<<<3125, 256>>>(ei, ew);
    k_scan1<<<49, 1024>>>();
    k_scan2<<<1, 64>>>();
    k_scan3<<<49, 1024>>>();
    k_scatter<<<3125, 256>>>(ei);
    k_rowsort<<<196, 256>>>();
    k_embed<<<256, 256>>>(x, tab);

    // layer 0
    k_lin<<<782, 256>>>(E_p, 64, d_p + D_EMB, egw, egb, egm, 0, cW, cB, invN);
    k_spmm_csr<<<800, 256>>>(0, d_p + D_G0, d_p + D_GL);
    // layer 1
    k_lin<<<782, 256>>>(hcat_p, 192, d_p + D_G0, gnw, gnb, gnm, 1, cW + 4096, cB + 64, invN);
    k_spmm_csr<<<800, 256>>>(64, d_p + D_G1, d_p + D_GL);
    // layer 2
    k_lin<<<782, 256>>>(hcat_p + 64, 192, d_p + D_G1, gnw + 64, gnb + 64, gnm + 64,
                        1, cW + 8192, cB + 128, invN);
    k_spmm_csr<<<800, 256>>>(128, (double*)0, d_p + D_GL);

    k_soft<<<296, 256>>>(sW, sb, d_p + D_GL, glw, glb, glm, invN);
    k_num<<<2048, 256>>>(ei, ew);
    k_sub2v2<<<128, 256>>>(SA);
    k_fin<<<1, 256>>>(out);
    k_embbuild<<<256, 256>>>();

    k_mlp1<<<256, 256>>>(pW1);
    k_mlptail<<<8, 256>>>(pb1, pW2, pb2, pW3, pb3, pW4, pb4, out);

    (void)in_sizes; (void)n_in; (void)out_size;
}

// round 14
// speedup vs baseline: 1.5736x; 1.0165x over previous
#include <cuda_runtime.h>
#include <math.h>

#define NN 50000
#define NE 800000
#define EPSV 1e-5

// ---------------- scratch (__device__ globals; no runtime alloc) ----------------
__device__ double g_degd[NN];          // fp64 degree (deterministic to 1e-16)
__device__ float  g_degf[NN];          // fp32 snapshot for mincut_den
__device__ float  g_normw[NE];
__device__ float  g_E[NN * 64];
__device__ float  g_hlin[NN * 64];
__device__ float  g_hcat[NN * 192];
__device__ float  g_ssmf[NN * 16];     // fp32 ssm (feeds key kernel — FROZEN)
__device__ float  g_outf[16 * 192];
__device__ float  g_emb[256 * 3088];
__device__ float  g_h1pre[256 * 128];
__device__ float  g_sub2f[16 * 256];   // fp32 sort keys (winning realization — FROZEN)

// CSR structures (built once per launch; rows canonically sorted -> deterministic)
__device__ int    g_cnt[NN];
__device__ int    g_cur[NN];
__device__ int    g_rowoff[NN + 1];
__device__ int2   g_csre[NE];          // (col, weight-bits)
__device__ int    g_rowtmp[50176];
__device__ int    g_bsum[64];

// fp64 accumulator zone (memset to 0 once per launch)
#define D_EMB    0      // 128
#define D_G0     128    // 128
#define D_G1     256    // 128
#define D_GL     384    // 384
#define D_COLSUM 768    // 16
#define D_SS     784    // 256
#define D_NUM    1040   // 1
#define D_DEN    1041   // 1
#define D_OUT    1048   // 3072
#define D_TOTAL  4120
__device__ double g_d[D_TOTAL];

// GraphNorm affine from fp64 stats (identical math across rounds)
__device__ __forceinline__ void affine_pair(const double* sums, const float* w,
        const float* b, const float* ms, int C, double invN, int c,
        float* a_out, float* c_out) {
    double mu = sums[c] * invN;
    double ex2 = sums[C + c] * invN;
    double m = (double)ms[c];
    double var = ex2 - 2.0 * m * mu * mu + m * m * mu * mu;
    double a = (double)w[c] / sqrt(var + EPSV);
    *a_out = (float)a;
    *c_out = (float)((double)b[c] - a * m * mu);
}

// ---------------- kernels ----------------

__global__ void k_deg(const int* ei, const float* ew) {
    int e = blockIdx.x * blockDim.x + threadIdx.x;
    if (e < NE) {
        atomicAdd(&g_degd[ei[e]], (double)ew[e]);
        atomicAdd(&g_cnt[ei[e]], 1);
    }
}

__global__ void k_norm(const int* ei, const float* ew) {
    int e = blockIdx.x * blockDim.x + threadIdx.x;
    if (e < NE) {
        double d = g_degd[ei[e]];
        if (d < 0.5) d += 1.0;
        g_normw[e] = (float)((double)ew[e] / d);
    }
    if (e < NN) g_degf[e] = (float)g_degd[e];
}

// 3-phase deterministic int scan
__global__ void k_scan1() {
    __shared__ int sh[1024];
    int t = threadIdx.x, b = blockIdx.x;
    int idx = b * 1024 + t;
    int v = (idx < NN) ? g_cnt[idx] : 0;
    sh[t] = v; __syncthreads();
    for (int s = 1; s < 1024; s <<= 1) {
        int add = (t >= s) ? sh[t - s] : 0;
        __syncthreads();
        sh[t] += add;
        __syncthreads();
    }
    g_rowtmp[idx] = sh[t];
    if (t == 1023) g_bsum[b] = sh[t];
}
__global__ void k_scan2() {
    if (threadIdx.x == 0) {
        int acc = 0;
        for (int i = 0; i < 49; i++) { int v = g_bsum[i]; g_bsum[i] = acc; acc += v; }
    }
}
__global__ void k_scan3() {
    int t = threadIdx.x, b = blockIdx.x;
    int idx = b * 1024 + t;
    if (idx < NN) g_rowoff[idx + 1] = g_rowtmp[idx] + g_bsum[b];
    if (idx == 0) g_rowoff[0] = 0;
}

__global__ void k_scatter(const int* ei) {
    int e = blockIdx.x * blockDim.x + threadIdx.x;
    if (e < NE) {
        int r = ei[e];
        int pos = g_rowoff[r] + atomicAdd(&g_cur[r], 1);
        g_csre[pos] = make_int2(ei[NE + e], __float_as_int(g_normw[e]));
    }
}

// canonicalize each CSR row by (col, weight-bits) ascending — FROZEN comparator.
// Warp-per-row bitonic sort (64 elems, 2 regs/lane). Equal keys are bit-identical,
// so the sorted sequence equals the old insertion sort's output exactly.
__global__ void k_rowsort() {
    int w = (blockIdx.x * blockDim.x + threadIdx.x) >> 5;
    int lane = threadIdx.x & 31;
    if (w >= NN) return;
    int j0 = g_rowoff[w], j1 = g_rowoff[w + 1];
    int deg = j1 - j0;
    if (deg <= 1) return;
    if (deg <= 64) {
        unsigned long long v0 = ~0ULL, v1 = ~0ULL;
        if (lane < deg) {
            int2 e = g_csre[j0 + lane];
            v0 = ((unsigned long long)(unsigned)e.x << 32) | (unsigned)e.y;
        }
        if (lane + 32 < deg) {
            int2 e = g_csre[j0 + 32 + lane];
            v1 = ((unsigned long long)(unsigned)e.x << 32) | (unsigned)e.y;
        }
        #pragma unroll
        for (int k = 2; k <= 64; k <<= 1) {
            #pragma unroll
            for (int j = k >> 1; j >= 1; j >>= 1) {
                if (j == 32) {   // only in k=64 stage; both directions ascending
                    unsigned long long mn = v0 < v1 ? v0 : v1;
                    unsigned long long mx = v0 < v1 ? v1 : v0;
                    v0 = mn; v1 = mx;
                } else {
                    bool up0 = ((lane & k) == 0) || (k == 64);
                    bool up1 = (k == 64) ? true
                             : (k == 32) ? false
                             : ((lane & k) == 0);
                    bool lowerHalf = ((lane & j) == 0);
                    unsigned long long o0 = __shfl_xor_sync(0xffffffffu, v0, j);
                    unsigned long long o1 = __shfl_xor_sync(0xffffffffu, v1, j);
                    bool tm0 = (lowerHalf == up0);
                    bool tm1 = (lowerHalf == up1);
                    v0 = tm0 ? (v0 < o0 ? v0 : o0) : (v0 > o0 ? v0 : o0);
                    v1 = tm1 ? (v1 < o1 ? v1 : o1) : (v1 > o1 ? v1 : o1);
                }
            }
        }
        if (lane < deg)
            g_csre[j0 + lane] = make_int2((int)(v0 >> 32), (int)(unsigned)(v0 & 0xffffffffu));
        if (lane + 32 < deg)
            g_csre[j0 + 32 + lane] = make_int2((int)(v1 >> 32), (int)(unsigned)(v1 & 0xffffffffu));
    } else if (lane == 0) {   // rare fallback: serial insertion (same comparator)
        for (int i = j0 + 1; i < j1; i++) {
            int2 e = g_csre[i];
            int j = i - 1;
            while (j >= j0) {
                int2 ej = g_csre[j];
                if (ej.x > e.x || (ej.x == e.x && (unsigned)ej.y > (unsigned)e.y)) {
                    g_csre[j + 1] = ej; j--;
                } else break;
            }
            g_csre[j + 1] = e;
        }
    }
}

// embedding gather (fp32) + per-channel sum/sumsq (fp64 accumulate)
__global__ void k_embed(const int* x, const float* tab) {
    int c = threadIdx.x & 63;
    int rbase = blockIdx.x * 4 + (threadIdx.x >> 6);
    double s = 0.0, s2 = 0.0;
    for (int r = rbase; r < NN; r += gridDim.x * 4) {
        float v = tab[x[r] * 64 + c];
        g_E[r * 64 + c] = v;
        double vd = (double)v;
        s += vd; s2 += vd * vd;
    }
    atomicAdd(&g_d[D_EMB + c], s);
    atomicAdd(&g_d[D_EMB + 64 + c], s2);
}

// node Linear fp32 with inlined GN affine: out = relu( f(in)*W + b )
__global__ void k_lin(const float* in, int ldin, const double* sums,
                      const float* gw, const float* gb, const float* gm,
                      int prerelu, const float* W, const float* bias, double invN) {
    __shared__ float Xs[64][65];
    __shared__ float Ws[64][64];
    __shared__ float as_[64], cs_[64], bs_[64];
    int tid = threadIdx.x;
    for (int i = tid; i < 4096; i += 256) Ws[i >> 6][i & 63] = W[i];
    if (tid < 64) {
        affine_pair(sums, gw, gb, gm, 64, invN, tid, &as_[tid], &cs_[tid]);
        bs_[tid] = bias[tid];
    }
    __syncthreads();
    int r0 = blockIdx.x * 64;
    for (int i = tid; i < 4096; i += 256) {
        int r = i >> 6, c = i & 63;
        int gr = r0 + r;
        float v = 0.f;
        if (gr < NN) {
            v = fmaf(as_[c], in[gr * ldin + c], cs_[c]);
            if (prerelu) v = fmaxf(v, 0.f);
        }
        Xs[r][c] = v;
    }
    __syncthreads();
    int c = (tid & 15) * 4, rr = tid >> 4;
    float acc[4][4] = {};
    for (int k = 0; k < 64; k++) {
        float4 wv = *(const float4*)&Ws[k][c];
        #pragma unroll
        for (int i = 0; i < 4; i++) {
            float xv = Xs[rr + 16 * i][k];
            acc[i][0] = fmaf(xv, wv.x, acc[i][0]);
            acc[i][1] = fmaf(xv, wv.y, acc[i][1]);
            acc[i][2] = fmaf(xv, wv.z, acc[i][2]);
            acc[i][3] = fmaf(xv, wv.w, acc[i][3]);
        }
    }
    for (int i = 0; i < 4; i++) {
        int gr = r0 + rr + 16 * i;
        if (gr < NN) {
            float4 o;
            o.x = fmaxf(acc[i][0] + bs_[c + 0], 0.f);
            o.y = fmaxf(acc[i][1] + bs_[c + 1], 0.f);
            o.z = fmaxf(acc[i][2] + bs_[c + 2], 0.f);
            o.w = fmaxf(acc[i][3] + bs_[c + 3], 0.f);
            *(float4*)&g_hlin[gr * 64 + c] = o;
        }
    }
}

// CSR gather-SpMM fp32 (FROZEN row compute) + fused GN channel stats (fp64)
__global__ void k_spmm_csr(int coloff, double* sL, double* sG) {
    __shared__ double sh[128];            // [0:64] sum, [64:128] sumsq
    int t = threadIdx.x, lane = t & 31, wid = t >> 5;
    if (t < 128) sh[t] = 0.0;
    __syncthreads();
    int w0 = blockIdx.x * 8 + wid;
    int stride = gridDim.x * 8;
    double s0 = 0.0, s1 = 0.0, q0 = 0.0, q1 = 0.0;
    for (int w = w0; w < NN; w += stride) {
        int j0 = g_rowoff[w], j1 = g_rowoff[w + 1];
        float a0 = 0.f, a1 = 0.f;
        for (int j = j0; j < j1; j++) {
            int2 e = g_csre[j];
            float wt = __int_as_float(e.y);
            float2 v = *(const float2*)&g_hlin[e.x * 64 + lane * 2];
            a0 = fmaf(wt, v.x, a0);
            a1 = fmaf(wt, v.y, a1);
        }
        float2 o = { a0, a1 };
        *(float2*)&g_hcat[w * 192 + coloff + lane * 2] = o;
        double d0 = (double)a0, d1 = (double)a1;
        s0 += d0; s1 += d1; q0 += d0 * d0; q1 += d1 * d1;
    }
    atomicAdd(&sh[lane * 2 + 0], s0);
    atomicAdd(&sh[lane * 2 + 1], s1);
    atomicAdd(&sh[64 + lane * 2 + 0], q0);
    atomicAdd(&sh[64 + lane * 2 + 1], q1);
    __syncthreads();
    if (t < 64) {
        double ssum = sh[t], sq = sh[64 + t];
        atomicAdd(&sG[coloff + t], ssum);
        atomicAdd(&sG[192 + coloff + t], sq);
        if (sL) {
            atomicAdd(&sL[t], ssum);
            atomicAdd(&sL[64 + t], sq);
        }
    }
}

// s = gn(hcat) @ sW + sb, softmax (FROZEN g_ssmf realization); fused fp64
// partials (colsum, ss, den) + merged poolout partials.
__global__ void k_soft(const float* sW, const float* sb, const double* sums,
                       const float* glw, const float* glb, const float* glm,
                       double invN) {
    __shared__ float H[32][193];
    __shared__ float Ws[3072];
    __shared__ float Sm[32][17];
    __shared__ float sbs[16];
    __shared__ float af[192], cf[192];
    int t = threadIdx.x;
    for (int i = t; i < 3072; i += 256) Ws[i] = sW[i];
    if (t < 16) sbs[t] = sb[t];
    if (t < 192) affine_pair(sums, glw, glb, glm, 192, invN, t, &af[t], &cf[t]);
    int a_ = t >> 4, b_ = t & 15;
    int kp = t & 15, fbp = (t >> 4) * 12;
    double ss_acc = 0.0, col_acc = 0.0, den_acc = 0.0;
    float po[12];
    #pragma unroll
    for (int j = 0; j < 12; j++) po[j] = 0.f;
    for (int tile = blockIdx.x; tile < 1563; tile += gridDim.x) {
        int n0 = tile * 32;
        __syncthreads();
        for (int i = t; i < 32 * 192; i += 256) {
            int r = i / 192, f = i - r * 192;
            int gr = n0 + r;
            H[r][f] = (gr < NN) ? fmaf(af[f], g_hcat[gr * 192 + f], cf[f]) : 0.f;
        }
        __syncthreads();
        #pragma unroll
        for (int p = 0; p < 2; p++) {
            int i = a_ + 16 * p;
            float acc = 0.f;
            for (int f = 0; f < 192; f++) acc = fmaf(H[i][f], Ws[f * 16 + b_], acc);
            Sm[i][b_] = acc + sbs[b_];
        }
        __syncthreads();
        if (t < 32) {
            int gr = n0 + t;
            if (gr < NN) {
                float mx = -1e30f;
                #pragma unroll
                for (int j = 0; j < 16; j++) mx = fmaxf(mx, Sm[t][j]);
                float ev[16]; float s = 0.f;
                #pragma unroll
                for (int j = 0; j < 16; j++) { ev[j] = expf(Sm[t][j] - mx); s += ev[j]; }
                float inv = 1.f / s;
                float sq = 0.f;
                #pragma unroll
                for (int j = 0; j < 16; j++) {
                    float v = ev[j] * inv;
                    Sm[t][j] = v;
                    g_ssmf[gr * 16 + j] = v;
                    sq += v * v;
                }
                den_acc += (double)(g_degf[gr] * sq);
            } else {
                #pragma unroll
                for (int j = 0; j < 16; j++) Sm[t][j] = 0.f;
            }
        }
        __syncthreads();
        {
            float s = 0.f;
            #pragma unroll
            for (int i = 0; i < 32; i++) s += Sm[i][a_] * Sm[i][b_];
            ss_acc += (double)s;
        }
        if (t < 16) {
            float s = 0.f;
            #pragma unroll
            for (int i = 0; i < 32; i++) s += Sm[i][t];
            col_acc += (double)s;
        }
        #pragma unroll 4
        for (int i = 0; i < 32; i++) {
            float sv = Sm[i][kp];
            #pragma unroll
            for (int j = 0; j < 12; j++) po[j] = fmaf(sv, H[i][fbp + j], po[j]);
        }
    }
    atomicAdd(&g_d[D_SS + t], ss_acc);
    if (t < 16) atomicAdd(&g_d[D_COLSUM + t], col_acc);
    if (t < 32) atomicAdd(&g_d[D_DEN], den_acc);
    for (int j = 0; j < 12; j++)
        atomicAdd(&g_d[D_OUT + kp * 192 + fbp + j], (double)po[j]);
}

// mincut numerator: sum_e w[e] * <ssm[row], ssm[col]>  (fp32 dot, fp64 reduce)
__global__ void k_num(const int* ei, const float* ew) {
    float acc = 0.f;
    for (int e = blockIdx.x * blockDim.x + threadIdx.x; e < NE;
         e += gridDim.x * blockDim.x) {
        int r = ei[e], c = ei[NE + e];
        const float4* a = (const float4*)&g_ssmf[r * 16];
        const float4* b = (const float4*)&g_ssmf[c * 16];
        float d = 0.f;
        #pragma unroll
        for (int i = 0; i < 4; i++) {
            float4 av = a[i], bv = b[i];
            d += av.x * bv.x + av.y * bv.y + av.z * bv.z + av.w * bv.w;
        }
        acc = fmaf(ew[e], d, acc);
    }
    __shared__ double red[256];
    red[threadIdx.x] = (double)acc; __syncthreads();
    for (int s = 128; s > 0; s >>= 1) {
        if (threadIdx.x < s) red[threadIdx.x] += red[threadIdx.x + s];
        __syncthreads();
    }
    if (threadIdx.x == 0) atomicAdd(&g_d[D_NUM], red[0]);
}

// ======= sort keys: FROZEN per-(k,m) realization; 2 subgraphs per block =======
#define S2CH 512
__global__ void k_sub2v2(const float* SA) {
    __shared__ float sss[S2CH * 17];
    __shared__ float sa0[S2CH], sa1[S2CH];
    __shared__ float lr[2][16][17];
    int t = threadIdx.x;
    int k = t >> 4, lane = t & 15;
    int m0 = blockIdx.x, m1 = blockIdx.x + 128;
    float cs = (float)g_d[D_COLSUM + k];
    if (cs < 1e-12f) cs = 1e-12f;
    const float* sA0 = SA + (size_t)m0 * NN;
    const float* sA1 = SA + (size_t)m1 * NN;
    float acc0 = 0.f, acc1 = 0.f;
    for (int n0 = 0; n0 < NN; n0 += S2CH) {
        int span = NN - n0; if (span > S2CH) span = S2CH;
        __syncthreads();
        for (int i = t; i < span * 16; i += 256) {
            int n2 = i >> 4, kk = i & 15;
            sss[n2 * 17 + kk] = g_ssmf[(n0 + n2) * 16 + kk];
        }
        for (int i = t; i < span; i += 256) { sa0[i] = sA0[n0 + i]; sa1[i] = sA1[n0 + i]; }
        __syncthreads();
        for (int n2 = lane; n2 < span; n2 += 16) {
            float sv = sss[n2 * 17 + k];
            float tv = sv / cs;
            acc0 = fmaf(tv, sa0[n2], acc0);
            acc1 = fmaf(tv, sa1[n2], acc1);
        }
    }
    lr[0][k][lane] = acc0; lr[1][k][lane] = acc1;
    __syncthreads();
    for (int s = 8; s > 0; s >>= 1) {
        if (lane < s) {
            lr[0][k][lane] += lr[0][k][lane + s];
            lr[1][k][lane] += lr[1][k][lane + s];
        }
        __syncthreads();
    }
    if (lane == 0) {
        g_sub2f[k * 256 + m0] = lr[0][k][0];
        g_sub2f[k * 256 + m1] = lr[1][k][0];
    }
}

// losses (fp64) + out conversion
__global__ void k_fin(float* dout) {
    int t = threadIdx.x;
    __shared__ double red[256];
    __shared__ double fro;
    for (int idx = t; idx < 3072; idx += 256)
        g_outf[idx] = (float)g_d[D_OUT + idx];
    double v = g_d[D_SS + t];
    red[t] = v * v; __syncthreads();
    for (int s = 128; s > 0; s >>= 1) { if (t < s) red[t] += red[t + s]; __syncthreads(); }
    if (t == 0) fro = sqrt(red[0]);
    __syncthreads();
    double d = v / fro - (((t >> 4) == (t & 15)) ? 0.25 : 0.0);
    red[t] = d * d; __syncthreads();
    for (int s = 128; s > 0; s >>= 1) { if (t < s) red[t] += red[t + s]; __syncthreads(); }
    if (t == 0) {
        dout[16385] = (float)sqrt(red[0]);
        dout[16384] = (float)(-(g_d[D_NUM] / g_d[D_DEN]));
    }
}

// per-subgraph: stable sort clusters by fp32 score desc, emit emb row (fp32)
__global__ void k_embbuild() {
    __shared__ float rs[16];
    __shared__ int perm[16];
    int m = blockIdx.x, t = threadIdx.x;
    if (t < 16) rs[t] = g_sub2f[t * 256 + m];
    __syncthreads();
    if (t == 0) {
        int p[16];
        for (int i = 0; i < 16; i++) p[i] = i;
        for (int i = 1; i < 16; i++) {
            int key = p[i]; float kv = rs[key];
            int j = i - 1;
            while (j >= 0 && rs[p[j]] < kv) { p[j + 1] = p[j]; j--; }
            p[j + 1] = key;
        }
        for (int i = 0; i < 16; i++) perm[i] = p[i];
    }
    __syncthreads();
    for (int idx = t; idx < 3088; idx += 256) {
        int j = idx / 193, f = idx - j * 193;
        int pk = perm[j];
        g_emb[m * 3088 + idx] = (f < 192) ? g_outf[pk * 192 + f] : rs[pk];
    }
}

// MLP layer 1: 256x3088 @ 3088x128 fp32, split-K=16 with fp32 atomic accumulate
__global__ void k_mlp1(const float* W1) {
    int b = blockIdx.x;
    int rt = b & 7; b >>= 3; int ct = b & 1; int ks = b >> 1;
    int r0 = rt * 32, c0 = ct * 64, k0 = ks * 193;
    __shared__ float As[32][33];
    __shared__ float Bs[32][64];
    int t = threadIdx.x;
    int c = (t & 15) * 4, rr = (t >> 4) * 2;
    float acc[2][4] = {};
    for (int kk = 0; kk < 193; kk += 32) {
        int kc = 193 - kk; if (kc > 32) kc = 32;
        for (int i = t; i < 32 * 32; i += 256) {
            int r = i >> 5, kx = i & 31;
            As[r][kx] = (kx < kc) ? g_emb[(r0 + r) * 3088 + k0 + kk + kx] : 0.f;
        }
        for (int i = t; i < 32 * 64; i += 256) {
            int kx = i >> 6, cc = i & 63;
            Bs[kx][cc] = (kx < kc) ? W1[(k0 + kk + kx) * 128 + c0 + cc] : 0.f;
        }
        __syncthreads();
        #pragma unroll 8
        for (int kx = 0; kx < 32; kx++) {
            float4 bv = *(const float4*)&Bs[kx][c];
            float a0 = As[rr][kx], a1 = As[rr + 1][kx];
            acc[0][0] = fmaf(a0, bv.x, acc[0][0]); acc[0][1] = fmaf(a0, bv.y, acc[0][1]);
            acc[0][2] = fmaf(a0, bv.z, acc[0][2]); acc[0][3] = fmaf(a0, bv.w, acc[0][3]);
            acc[1][0] = fmaf(a1, bv.x, acc[1][0]); acc[1][1] = fmaf(a1, bv.y, acc[1][1]);
            acc[1][2] = fmaf(a1, bv.z, acc[1][2]); acc[1][3] = fmaf(a1, bv.w, acc[1][3]);
        }
        __syncthreads();
    }
    for (int i = 0; i < 2; i++)
        for (int j = 0; j < 4; j++)
            atomicAdd(&g_h1pre[(r0 + rr + i) * 128 + c0 + c + j], acc[i][j]);
}

// MLP tail: bias+relu then layers 2,3,4 in one kernel (row-local, deterministic)
__global__ void k_mlptail(const float* b1, const float* W2, const float* b2,
                          const float* W3, const float* b3,
                          const float* W4, const float* b4, float* out) {
    __shared__ float Hs[32][129];
    __shared__ float Bs[32][128];
    int t = threadIdx.x;
    int r0 = blockIdx.x * 32;
    for (int i = t; i < 32 * 128; i += 256) {
        int r = i >> 7, c = i & 127;
        Hs[r][c] = fmaxf(g_h1pre[(r0 + r) * 128 + c] + b1[c], 0.f);
    }
    __syncthreads();
    int c8 = (t & 15) * 8, rr = (t >> 4) * 2;
    for (int layer = 0; layer < 2; layer++) {
        const float* W = layer ? W3 : W2;
        const float* bb = layer ? b3 : b2;
        float acc[2][8] = {};
        for (int k0 = 0; k0 < 128; k0 += 32) {
            for (int i = t; i < 32 * 128; i += 256) {
                int kx = i >> 7, cc = i & 127;
                Bs[kx][cc] = W[(k0 + kx) * 128 + cc];
            }
            __syncthreads();
            for (int kx = 0; kx < 32; kx++) {
                float h0 = Hs[rr][k0 + kx], h1v = Hs[rr + 1][k0 + kx];
                #pragma unroll
                for (int j = 0; j < 8; j++) {
                    float w = Bs[kx][c8 + j];
                    acc[0][j] = fmaf(h0, w, acc[0][j]);
                    acc[1][j] = fmaf(h1v, w, acc[1][j]);
                }
            }
            __syncthreads();
        }
        #pragma unroll
        for (int i = 0; i < 2; i++)
            #pragma unroll
            for (int j = 0; j < 8; j++)
                Hs[rr + i][c8 + j] = fmaxf(acc[i][j] + bb[c8 + j], 0.f);
        __syncthreads();
    }
    {   // layer 4: 128 -> 64
        int c4 = (t & 15) * 4;
        float acc[2][4] = {};
        for (int k0 = 0; k0 < 128; k0 += 32) {
            for (int i = t; i < 32 * 64; i += 256) {
                int kx = i >> 6, cc = i & 63;
                Bs[kx][cc] = W4[(k0 + kx) * 64 + cc];
            }
            __syncthreads();
            for (int kx = 0; kx < 32; kx++) {
                float h0 = Hs[rr][k0 + kx], h1v = Hs[rr + 1][k0 + kx];
                #pragma unroll
                for (int j = 0; j < 4; j++) {
                    float w = Bs[kx][c4 + j];
                    acc[0][j] = fmaf(h0, w, acc[0][j]);
                    acc[1][j] = fmaf(h1v, w, acc[1][j]);
                }
            }
            __syncthreads();
        }
        #pragma unroll
        for (int i = 0; i < 2; i++)
            #pragma unroll
            for (int j = 0; j < 4; j++)
                out[(r0 + rr + i) * 64 + c4 + j] = acc[i][j] + b4[c4 + j];
    }
}

// ---------------- launch ----------------
extern "C" void kernel_launch(void* const* d_in, const int* in_sizes, int n_in,
                              void* d_out, int out_size) {
    const int*   x    = (const int*)d_in[0];
    const int*   ei   = (const int*)d_in[1];
    const float* ew   = (const float*)d_in[2];
    const float* SA   = (const float*)d_in[4];
    const float* tab  = (const float*)d_in[5];
    const float* egw  = (const float*)d_in[6];
    const float* egb  = (const float*)d_in[7];
    const float* egm  = (const float*)d_in[8];
    const float* cW   = (const float*)d_in[9];
    const float* cB   = (const float*)d_in[10];
    const float* gnw  = (const float*)d_in[11];
    const float* gnb  = (const float*)d_in[12];
    const float* gnm  = (const float*)d_in[13];
    const float* glw  = (const float*)d_in[14];
    const float* glb  = (const float*)d_in[15];
    const float* glm  = (const float*)d_in[16];
    const float* sW   = (const float*)d_in[17];
    const float* sb   = (const float*)d_in[18];
    const float* pW1  = (const float*)d_in[19];
    const float* pb1  = (const float*)d_in[20];
    const float* pW2  = (const float*)d_in[21];
    const float* pb2  = (const float*)d_in[22];
    const float* pW3  = (const float*)d_in[23];
    const float* pb3  = (const float*)d_in[24];
    const float* pW4  = (const float*)d_in[25];
    const float* pb4  = (const float*)d_in[26];
    float* out = (float*)d_out;

    void *pv;
    float *E_p, *hcat_p, *h1pre_p;
    double *degd_p, *d_p;
    int *cnt_p, *cur_p;
    cudaGetSymbolAddress(&pv, g_degd);    degd_p  = (double*)pv;
    cudaGetSymbolAddress(&pv, g_E);       E_p     = (float*)pv;
    cudaGetSymbolAddress(&pv, g_hcat);    hcat_p  = (float*)pv;
    cudaGetSymbolAddress(&pv, g_h1pre);   h1pre_p = (float*)pv;
    cudaGetSymbolAddress(&pv, g_d);       d_p     = (double*)pv;
    cudaGetSymbolAddress(&pv, g_cnt);     cnt_p   = (int*)pv;
    cudaGetSymbolAddress(&pv, g_cur);     cur_p   = (int*)pv;

    cudaMemsetAsync(degd_p, 0, (size_t)NN * 8);
    cudaMemsetAsync(h1pre_p, 0, (size_t)256 * 128 * 4);
    cudaMemsetAsync(d_p, 0, (size_t)D_TOTAL * 8);
    cudaMemsetAsync(cnt_p, 0, (size_t)NN * 4);
    cudaMemsetAsync(cur_p, 0, (size_t)NN * 4);

    const double invN = 1.0 / (double)NN;

    k_deg<<<3125, 256>>>(ei, ew);
    k_norm<<<3125, 256>>>(ei, ew);
    k_scan1<<<49, 1024>>>();
    k_scan2<<<1, 64>>>();
    k_scan3<<<49, 1024>>>();
    k_scatter<<<3125, 256>>>(ei);
    k_rowsort<<<6250, 256>>>();
    k_embed<<<256, 256>>>(x, tab);

    // layer 0
    k_lin<<<782, 256>>>(E_p, 64, d_p + D_EMB, egw, egb, egm, 0, cW, cB, invN);
    k_spmm_csr<<<800, 256>>>(0, d_p + D_G0, d_p + D_GL);
    // layer 1
    k_lin<<<782, 256>>>(hcat_p, 192, d_p + D_G0, gnw, gnb, gnm, 1, cW + 4096, cB + 64, invN);
    k_spmm_csr<<<800, 256>>>(64, d_p + D_G1, d_p + D_GL);
    // layer 2
    k_lin<<<782, 256>>>(hcat_p + 64, 192, d_p + D_G1, gnw + 64, gnb + 64, gnm + 64,
                        1, cW + 8192, cB + 128, invN);
    k_spmm_csr<<<800, 256>>>(128, (double*)0, d_p + D_GL);

    k_soft<<<296, 256>>>(sW, sb, d_p + D_GL, glw, glb, glm, invN);
    k_num<<<2048, 256>>>(ei, ew);
    k_sub2v2<<<128, 256>>>(SA);
    k_fin<<<1, 256>>>(out);
    k_embbuild<<<256, 256>>>();

    k_mlp1<<<256, 256>>>(pW1);
    k_mlptail<<<8, 256>>>(pb1, pW2, pb2, pW3, pb3, pW4, pb4, out);

    (void)in_sizes; (void)n_in; (void)out_size;
}